// round 15
// baseline (speedup 1.0000x reference)
#include <cuda_runtime.h>
#include <math.h>
#include <stdint.h>

#define N_NODES 50000
#define N_EDGES 800000

// ----------------- device-global scratch (no allocations) -----------------
__device__ __align__(16) float g_WEt[128 * 160];   // k-major: [k][0..127]=inter_w1@bond, [k][128..159]=gate edge slice
__device__ __align__(16) float g_WMLt[128 * 128];  // [j][p] = (inter_w1 @ nodeb[:, :128])[p][j]
__device__ __align__(16) float g_WMRt[128 * 128];
__device__ __align__(16) float g_GLt[128 * 32];    // [j][q] = gate_w1[q][128+j]
__device__ __align__(16) float g_GRt[128 * 32];    // [j][q] = gate_w1[q][256+j]
__device__ __align__(16) float g_l1t[128 * 128];   // k-major transposes
__device__ __align__(16) float g_l2t[128 * 128];
__device__ __align__(16) float g_r1t[128 * 128];
__device__ __align__(16) float g_r2t[128 * 128];
__device__ __align__(16) float g_s1t[131 * 128];
__device__ __align__(16) float g_SRC[(size_t)N_NODES * 160];
__device__ __align__(16) float g_DST[(size_t)N_NODES * 160];
__device__ __align__(16) float g_delta[N_NODES * 3];
__device__ int g_idx_is64;

// ----------------- f32x2 helpers (Blackwell FFMA2, PTX-only) -----------------
__device__ __forceinline__ unsigned long long bc2(float x) {
    unsigned long long r;
    asm("mov.b64 %0, {%1, %1};" : "=l"(r) : "f"(x));
    return r;
}
__device__ __forceinline__ float2 up2(unsigned long long v) {
    float2 r;
    asm("mov.b64 {%0, %1}, %2;" : "=f"(r.x), "=f"(r.y) : "l"(v));
    return r;
}
#define FMA2(accv, av, bv) asm("fma.rn.f32x2 %0, %1, %2, %0;" : "+l"(accv) : "l"(av), "l"(bv))

// ----------------- P0: fold + transpose weights, zero delta, detect idx dtype
__global__ void prep_kernel(const float* __restrict__ iw1, const float* __restrict__ bond,
                            const float* __restrict__ nodeb, const float* __restrict__ gw1,
                            const float* __restrict__ lw1, const float* __restrict__ lw2,
                            const float* __restrict__ rw1, const float* __restrict__ rw2,
                            const float* __restrict__ sw1, const long long* __restrict__ ei)
{
    int b = blockIdx.x, t = threadIdx.x;
    float a = 0.f, c = 0.f, d = 0.f;
    for (int m = 0; m < 128; m++) {
        float w = iw1[t * 128 + m];
        a = fmaf(w, bond[m * 128 + b], a);
        c = fmaf(w, nodeb[m * 256 + b], c);
        d = fmaf(w, nodeb[m * 256 + 128 + b], d);
    }
    g_WEt[b * 160 + t]  = a;   // (iw1@bond)[t][b] at [k=b][p=t]
    g_WMLt[b * 128 + t] = c;
    g_WMRt[b * 128 + t] = d;
    if (t < 32) {
        g_WEt[b * 160 + 128 + t] = gw1[t * 386 + b];
        g_GLt[b * 32 + t] = gw1[t * 386 + 128 + b];
        g_GRt[b * 32 + t] = gw1[t * 386 + 256 + b];
    }
    g_l1t[b * 128 + t] = lw1[t * 128 + b];
    g_l2t[b * 128 + t] = lw2[t * 128 + b];
    g_r1t[b * 128 + t] = rw1[t * 128 + b];
    g_r2t[b * 128 + t] = rw2[t * 128 + b];
    g_s1t[b * 128 + t] = sw1[t * 131 + b];
    if (b < 3) g_s1t[(128 + b) * 128 + t] = sw1[t * 131 + 128 + b];
    for (int i = b * 128 + t; i < N_NODES * 3; i += 16384) g_delta[i] = 0.f;
    if (b == 0 && t == 0) {
        int ok = 1;
        for (int e = 0; e < 64; e++) {
            long long v = ei[e];
            if (v < 0 || v >= (long long)N_NODES) { ok = 0; break; }
        }
        g_idx_is64 = ok;
    }
}

// ----------------- P1: per-node tables -----------------
__device__ __forceinline__ void load_w(float* s_w, const float* g, int n_f4, int tid) {
    __syncthreads();
    for (int idx = tid; idx < n_f4; idx += 256)
        ((float4*)s_w)[idx] = ((const float4*)g)[idx];
    __syncthreads();
}

__device__ __forceinline__ void dense128(const float* __restrict__ s_in, const float* __restrict__ s_w,
                                         const float* __restrict__ bias, float* out, int ostride,
                                         int j, int half, int nn, int do_relu)
{
    for (int i0 = half * 8; i0 < nn; i0 += 16) {
        float acc[8];
        float b = bias ? bias[j] : 0.f;
        #pragma unroll
        for (int i = 0; i < 8; i++) acc[i] = b;
        int ilim = nn - i0; if (ilim > 8) ilim = 8;
        for (int k0 = 0; k0 < 128; k0 += 4) {
            float w0 = s_w[k0 * 128 + j], w1 = s_w[(k0 + 1) * 128 + j];
            float w2 = s_w[(k0 + 2) * 128 + j], w3 = s_w[(k0 + 3) * 128 + j];
            #pragma unroll
            for (int i = 0; i < 8; i++) {
                if (i < ilim) {
                    float4 xv = *(const float4*)(s_in + (i0 + i) * 128 + k0);
                    acc[i] = fmaf(xv.x, w0, acc[i]); acc[i] = fmaf(xv.y, w1, acc[i]);
                    acc[i] = fmaf(xv.z, w2, acc[i]); acc[i] = fmaf(xv.w, w3, acc[i]);
                }
            }
        }
        #pragma unroll
        for (int i = 0; i < 8; i++)
            if (i < ilim) {
                float v = acc[i];
                if (do_relu) v = fmaxf(v, 0.f);
                out[(i0 + i) * ostride + j] = v;
            }
    }
}

__device__ __forceinline__ void gate_stage(const float* __restrict__ s_f, const float* __restrict__ s_w,
                                           float* gtab, int n0, int nn, int tid,
                                           const float* __restrict__ gw1, const float* __restrict__ gb1,
                                           const float* __restrict__ extra, int with_extra)
{
    int q = tid & 31, s8 = tid >> 5;
    for (int i = s8; i < nn; i += 8) {
        float g = with_extra ? gb1[q] : 0.f;
        for (int k0 = 0; k0 < 128; k0 += 4) {
            float4 xv = *(const float4*)(s_f + i * 128 + k0);
            g = fmaf(xv.x, s_w[k0 * 32 + q], g);
            g = fmaf(xv.y, s_w[(k0 + 1) * 32 + q], g);
            g = fmaf(xv.z, s_w[(k0 + 2) * 32 + q], g);
            g = fmaf(xv.w, s_w[(k0 + 3) * 32 + q], g);
        }
        int n = n0 + i;
        if (with_extra)
            g += gw1[q * 386 + 384] * extra[n * 2] + gw1[q * 386 + 385] * extra[n * 2 + 1];
        gtab[(size_t)n * 160 + 128 + q] = g;
    }
}

__global__ __launch_bounds__(256, 1) void node_kernel(
    const float* __restrict__ h_node, const float* __restrict__ extra,
    const float* __restrict__ gw1,
    const float* __restrict__ lb1, const float* __restrict__ lb2,
    const float* __restrict__ rb1, const float* __restrict__ rb2,
    const float* __restrict__ ib1, const float* __restrict__ gb1)
{
    extern __shared__ float sm[];
    float* s_x = sm;                // 64*128
    float* s_h = sm + 8192;
    float* s_f = sm + 16384;
    float* s_w = sm + 24576;        // 128*128
    int tid = threadIdx.x, j = tid & 127, half = tid >> 7;
    int n0 = blockIdx.x * 64;
    int nn = N_NODES - n0; if (nn > 64) nn = 64;

    for (int idx = tid; idx < nn * 32; idx += 256)
        ((float4*)s_x)[idx] = ((const float4*)(h_node + (size_t)n0 * 128))[idx];

    load_w(s_w, g_l1t, 4096, tid);
    dense128(s_x, s_w, lb1, s_h, 128, j, half, nn, 1);
    load_w(s_w, g_l2t, 4096, tid);
    dense128(s_h, s_w, lb2, s_f, 128, j, half, nn, 0);
    load_w(s_w, g_WMLt, 4096, tid);
    dense128(s_f, s_w, ib1, g_SRC + (size_t)n0 * 160, 160, j, half, nn, 0);
    load_w(s_w, g_GLt, 1024, tid);
    gate_stage(s_f, s_w, g_SRC, n0, nn, tid, gw1, gb1, extra, 1);

    load_w(s_w, g_r1t, 4096, tid);
    dense128(s_x, s_w, rb1, s_h, 128, j, half, nn, 1);
    load_w(s_w, g_r2t, 4096, tid);
    dense128(s_h, s_w, rb2, s_f, 128, j, half, nn, 0);
    load_w(s_w, g_WMRt, 4096, tid);
    dense128(s_f, s_w, (const float*)0, g_DST + (size_t)n0 * 160, 160, j, half, nn, 0);
    load_w(s_w, g_GRt, 1024, tid);
    gate_stage(s_f, s_w, g_DST, n0, nn, tid, gw1, gb1, extra, 0);
}

// ----------------- P2: per-edge GEMM (f32x2) + epilogue + scatter ----------
__global__ __launch_bounds__(256, 1) void edge_kernel(
    const float* __restrict__ h_edge, const long long* __restrict__ ei64,
    const int* __restrict__ ei32, const float* __restrict__ rel,
    const float* __restrict__ dist,
    const float* __restrict__ iw2, const float* __restrict__ ib2,
    const float* __restrict__ gw2, const float* __restrict__ gb2)
{
    extern __shared__ float sm[];
    float* s_w   = sm;            // 20480 floats (weights), later y stride 129
    float* s_x   = sm + 20480;    // 16384
    float* s_iw2 = sm + 36864;    // 128
    float* s_gw2 = sm + 36992;    // 32
    float* s_int = sm + 37024;    // 128
    int*   s_el  = (int*)(sm + 37152);
    int*   s_er  = s_el + 128;
    int tid = threadIdx.x;
    size_t eb = (size_t)blockIdx.x * 128;

    for (int idx = tid; idx < 5120; idx += 256)
        ((float4*)s_w)[idx] = ((const float4*)g_WEt)[idx];
    {
        const float4* src = (const float4*)(h_edge + eb * 128);
        for (int idx = tid; idx < 4096; idx += 256) ((float4*)s_x)[idx] = src[idx];
    }
    if (tid < 128) {
        s_iw2[tid] = iw2[tid];
        if (tid < 32) s_gw2[tid] = gw2[tid];
        if (g_idx_is64) {
            s_el[tid] = (int)ei64[eb + tid];
            s_er[tid] = (int)ei64[N_EDGES + eb + tid];
        } else {
            s_el[tid] = ei32[eb + tid];
            s_er[tid] = ei32[N_EDGES + eb + tid];
        }
    }
    __syncthreads();

    int og = tid & 15, eg = tid >> 4;
    int o0 = og * 10, e0 = eg * 8;
    unsigned long long acc[8][5];
    #pragma unroll
    for (int i = 0; i < 8; i++)
        #pragma unroll
        for (int p = 0; p < 5; p++) acc[i][p] = 0ull;

    for (int k0 = 0; k0 < 128; k0 += 4) {
        float4 xv[8];
        #pragma unroll
        for (int i = 0; i < 8; i++)
            xv[i] = *(const float4*)(s_x + (e0 + i) * 128 + k0);
        #pragma unroll
        for (int kk = 0; kk < 4; kk++) {
            const unsigned long long* wr =
                (const unsigned long long*)(s_w + (k0 + kk) * 160 + o0);
            unsigned long long w0 = wr[0], w1 = wr[1], w2 = wr[2], w3 = wr[3], w4 = wr[4];
            #pragma unroll
            for (int i = 0; i < 8; i++) {
                unsigned long long xb = bc2(((const float*)&xv[i])[kk]);
                FMA2(acc[i][0], xb, w0); FMA2(acc[i][1], xb, w1);
                FMA2(acc[i][2], xb, w2); FMA2(acc[i][3], xb, w3);
                FMA2(acc[i][4], xb, w4);
            }
        }
    }
    __syncthreads();        // all reads of s_w / s_x done
    float* y = sm;          // y[o*129 + e], padded stride kills STS conflicts
    #pragma unroll
    for (int p = 0; p < 5; p++)
        #pragma unroll
        for (int i = 0; i < 8; i++) {
            float2 v = up2(acc[i][p]);
            y[(o0 + 2 * p) * 129 + e0 + i]     = v.x;
            y[(o0 + 2 * p + 1) * 129 + e0 + i] = v.y;
        }
    __syncthreads();

    float gate_v = 0.f;
    if (tid < 128) {                // inter dot for edge e = tid
        int e = tid, el = s_el[e], er = s_er[e];
        const float4* S = (const float4*)(g_SRC + (size_t)el * 160);
        const float4* D = (const float4*)(g_DST + (size_t)er * 160);
        float s = 0.f;
        #pragma unroll 4
        for (int j4 = 0; j4 < 32; j4++) {
            float4 u = S[j4], v = D[j4];
            int j = j4 * 4;
            s = fmaf(fmaxf(y[j * 129 + e] + u.x + v.x, 0.f), s_iw2[j], s);
            s = fmaf(fmaxf(y[(j + 1) * 129 + e] + u.y + v.y, 0.f), s_iw2[j + 1], s);
            s = fmaf(fmaxf(y[(j + 2) * 129 + e] + u.z + v.z, 0.f), s_iw2[j + 2], s);
            s = fmaf(fmaxf(y[(j + 3) * 129 + e] + u.w + v.w, 0.f), s_iw2[j + 3], s);
        }
        s_int[e] = s + ib2[0];
    } else {                        // gate dot for edge e = tid-128
        int e = tid - 128, el = s_el[e], er = s_er[e];
        const float4* S = (const float4*)(g_SRC + (size_t)el * 160 + 128);
        const float4* D = (const float4*)(g_DST + (size_t)er * 160 + 128);
        float g = 0.f;
        #pragma unroll
        for (int q4 = 0; q4 < 8; q4++) {
            float4 u = S[q4], v = D[q4];
            int j = 128 + q4 * 4, q = q4 * 4;
            g = fmaf(fmaxf(y[j * 129 + e] + u.x + v.x, 0.f), s_gw2[q], g);
            g = fmaf(fmaxf(y[(j + 1) * 129 + e] + u.y + v.y, 0.f), s_gw2[q + 1], g);
            g = fmaf(fmaxf(y[(j + 2) * 129 + e] + u.z + v.z, 0.f), s_gw2[q + 2], g);
            g = fmaf(fmaxf(y[(j + 3) * 129 + e] + u.w + v.w, 0.f), s_gw2[q + 3], g);
        }
        gate_v = g + gb2[0];
    }
    __syncthreads();
    if (tid >= 128) {
        int e = tid - 128, el = s_el[e];
        float w = s_int[e] * (1.f / (1.f + expf(-gate_v)));
        float d = dist[eb + e];
        float coef = w * 5.f / ((d + 1e-6f) * (d + 5.f));
        size_t rb = (eb + e) * 3;
        atomicAdd(&g_delta[el * 3 + 0], coef * rel[rb + 0]);
        atomicAdd(&g_delta[el * 3 + 1], coef * rel[rb + 1]);
        atomicAdd(&g_delta[el * 3 + 2], coef * rel[rb + 2]);
    }
}

// ----------------- P3: norm + scale MLP + output -----------------
__global__ __launch_bounds__(128) void final_kernel(
    const float* __restrict__ h_node, const float* __restrict__ extra,
    const float* __restrict__ sb1, const float* __restrict__ sw2,
    const float* __restrict__ sb2, float* __restrict__ out)
{
    extern __shared__ float sm[];
    float* s_w   = sm;           // 131*128 = 16768
    float* s_in  = sm + 16768;   // 132
    float* s_red = sm + 16900;   // 128
    float* s_w2  = sm + 17028;   // 128
    int tid = threadIdx.x;
    for (int idx = tid; idx < 4192; idx += 128)
        ((float4*)s_w)[idx] = ((const float4*)g_s1t)[idx];
    s_w2[tid] = sw2[tid];
    float b1 = sb1[tid], b2v = sb2[0];
    int n0 = blockIdx.x * 32;
    for (int i = 0; i < 32; i++) {
        int n = n0 + i;
        if (n >= N_NODES) break;
        __syncthreads();
        s_in[tid] = h_node[(size_t)n * 128 + tid];
        if (tid == 0) {
            s_in[128] = extra[n * 2]; s_in[129] = extra[n * 2 + 1];
            float dx = g_delta[n * 3], dy = g_delta[n * 3 + 1], dz = g_delta[n * 3 + 2];
            s_in[130] = sqrtf(dx * dx + dy * dy + dz * dz);
        }
        __syncthreads();
        float acc = b1;
        #pragma unroll 8
        for (int k0 = 0; k0 < 128; k0 += 4) {
            float4 xv = *(const float4*)(s_in + k0);
            acc = fmaf(xv.x, s_w[k0 * 128 + tid], acc);
            acc = fmaf(xv.y, s_w[(k0 + 1) * 128 + tid], acc);
            acc = fmaf(xv.z, s_w[(k0 + 2) * 128 + tid], acc);
            acc = fmaf(xv.w, s_w[(k0 + 3) * 128 + tid], acc);
        }
        acc = fmaf(s_in[128], s_w[128 * 128 + tid], acc);
        acc = fmaf(s_in[129], s_w[129 * 128 + tid], acc);
        acc = fmaf(s_in[130], s_w[130 * 128 + tid], acc);
        s_red[tid] = fmaxf(acc, 0.f) * s_w2[tid];
        __syncthreads();
        for (int ofs = 64; ofs > 0; ofs >>= 1) {
            if (tid < ofs) s_red[tid] += s_red[tid + ofs];
            __syncthreads();
        }
        if (tid == 0) {
            float sc = 1.f / (1.f + expf(-(s_red[0] + b2v)));
            out[n * 3 + 0] = g_delta[n * 3 + 0] * sc;
            out[n * 3 + 1] = g_delta[n * 3 + 1] * sc;
            out[n * 3 + 2] = g_delta[n * 3 + 2] * sc;
        }
    }
}

// ----------------- launch -----------------
extern "C" void kernel_launch(void* const* d_in, const int* in_sizes, int n_in,
                              void* d_out, int out_size)
{
    const float* h_node = (const float*)d_in[0];
    const float* h_edge = (const float*)d_in[1];
    const void*  ei     = d_in[2];
    const float* rel    = (const float*)d_in[3];
    const float* dist   = (const float*)d_in[4];
    const float* extra  = (const float*)d_in[5];
    const float* lw1 = (const float*)d_in[6];  const float* lb1 = (const float*)d_in[7];
    const float* lw2 = (const float*)d_in[8];  const float* lb2 = (const float*)d_in[9];
    const float* rw1 = (const float*)d_in[10]; const float* rb1 = (const float*)d_in[11];
    const float* rw2 = (const float*)d_in[12]; const float* rb2 = (const float*)d_in[13];
    const float* bond  = (const float*)d_in[14];
    const float* nodeb = (const float*)d_in[15];
    const float* iw1 = (const float*)d_in[16]; const float* ib1 = (const float*)d_in[17];
    const float* iw2 = (const float*)d_in[18]; const float* ib2 = (const float*)d_in[19];
    const float* gw1 = (const float*)d_in[20]; const float* gb1 = (const float*)d_in[21];
    const float* gw2 = (const float*)d_in[22]; const float* gb2 = (const float*)d_in[23];
    const float* sw1 = (const float*)d_in[24]; const float* sb1 = (const float*)d_in[25];
    const float* sw2 = (const float*)d_in[26]; const float* sb2 = (const float*)d_in[27];

    const int NODE_SMEM = 163840;   // (3*8192 + 16384) * 4
    const int EDGE_SMEM = 149632;   // 37152*4 + 256*4
    const int FIN_SMEM  = 68624;    // 17156*4

    cudaFuncSetAttribute(node_kernel, cudaFuncAttributeMaxDynamicSharedMemorySize, NODE_SMEM);
    cudaFuncSetAttribute(edge_kernel, cudaFuncAttributeMaxDynamicSharedMemorySize, EDGE_SMEM);
    cudaFuncSetAttribute(final_kernel, cudaFuncAttributeMaxDynamicSharedMemorySize, FIN_SMEM);

    prep_kernel<<<128, 128>>>(iw1, bond, nodeb, gw1, lw1, lw2, rw1, rw2, sw1,
                              (const long long*)ei);
    node_kernel<<<(N_NODES + 63) / 64, 256, NODE_SMEM>>>(h_node, extra, gw1,
                                                         lb1, lb2, rb1, rb2, ib1, gb1);
    edge_kernel<<<N_EDGES / 128, 256, EDGE_SMEM>>>(h_edge, (const long long*)ei,
                                                   (const int*)ei, rel, dist,
                                                   iw2, ib2, gw2, gb2);
    final_kernel<<<(N_NODES + 31) / 32, 128, FIN_SMEM>>>(h_node, extra, sb1, sw2, sb2,
                                                         (float*)d_out);
}

// round 16
// speedup vs baseline: 1.1095x; 1.1095x over previous
#include <cuda_runtime.h>
#include <math.h>
#include <stdint.h>

#define N_NODES 50000
#define N_EDGES 800000

// ----------------- device-global scratch (no allocations) -----------------
__device__ __align__(16) float g_WEt[128 * 160];   // k-major: [k][0..127]=inter_w1@bond, [k][128..159]=gate edge slice
__device__ __align__(16) float g_WMLt[128 * 128];  // [j][p] = (inter_w1 @ nodeb[:, :128])[p][j]
__device__ __align__(16) float g_WMRt[128 * 128];
__device__ __align__(16) float g_GLt[128 * 32];    // [j][q] = gate_w1[q][128+j]
__device__ __align__(16) float g_GRt[128 * 32];    // [j][q] = gate_w1[q][256+j]
__device__ __align__(16) float g_l1t[128 * 128];   // k-major transposes
__device__ __align__(16) float g_l2t[128 * 128];
__device__ __align__(16) float g_r1t[128 * 128];
__device__ __align__(16) float g_r2t[128 * 128];
__device__ __align__(16) float g_s1t[132 * 128];   // 131 real rows + 1 zero pad row
__device__ __align__(16) float g_SRC[(size_t)N_NODES * 160];
__device__ __align__(16) float g_DST[(size_t)N_NODES * 160];
__device__ __align__(16) float g_delta[N_NODES * 3];
__device__ int g_idx_is64;

// ----------------- f32x2 helpers (Blackwell FFMA2, PTX-only) -----------------
__device__ __forceinline__ unsigned long long bc2(float x) {
    unsigned long long r;
    asm("mov.b64 %0, {%1, %1};" : "=l"(r) : "f"(x));
    return r;
}
__device__ __forceinline__ unsigned long long pk2(float x, float y) {
    unsigned long long r;
    asm("mov.b64 %0, {%1, %2};" : "=l"(r) : "f"(x), "f"(y));
    return r;
}
__device__ __forceinline__ float2 up2(unsigned long long v) {
    float2 r;
    asm("mov.b64 {%0, %1}, %2;" : "=f"(r.x), "=f"(r.y) : "l"(v));
    return r;
}
#define FMA2(accv, av, bv) asm("fma.rn.f32x2 %0, %1, %2, %0;" : "+l"(accv) : "l"(av), "l"(bv))

// ----------------- P0: fold + transpose weights, zero delta, detect idx dtype
__global__ void prep_kernel(const float* __restrict__ iw1, const float* __restrict__ bond,
                            const float* __restrict__ nodeb, const float* __restrict__ gw1,
                            const float* __restrict__ lw1, const float* __restrict__ lw2,
                            const float* __restrict__ rw1, const float* __restrict__ rw2,
                            const float* __restrict__ sw1, const long long* __restrict__ ei)
{
    int b = blockIdx.x, t = threadIdx.x;
    float a = 0.f, c = 0.f, d = 0.f;
    for (int m = 0; m < 128; m++) {
        float w = iw1[t * 128 + m];
        a = fmaf(w, bond[m * 128 + b], a);
        c = fmaf(w, nodeb[m * 256 + b], c);
        d = fmaf(w, nodeb[m * 256 + 128 + b], d);
    }
    g_WEt[b * 160 + t]  = a;
    g_WMLt[b * 128 + t] = c;
    g_WMRt[b * 128 + t] = d;
    if (t < 32) {
        g_WEt[b * 160 + 128 + t] = gw1[t * 386 + b];
        g_GLt[b * 32 + t] = gw1[t * 386 + 128 + b];
        g_GRt[b * 32 + t] = gw1[t * 386 + 256 + b];
    }
    g_l1t[b * 128 + t] = lw1[t * 128 + b];
    g_l2t[b * 128 + t] = lw2[t * 128 + b];
    g_r1t[b * 128 + t] = rw1[t * 128 + b];
    g_r2t[b * 128 + t] = rw2[t * 128 + b];
    g_s1t[b * 128 + t] = sw1[t * 131 + b];
    if (b < 3) g_s1t[(128 + b) * 128 + t] = sw1[t * 131 + 128 + b];
    if (b == 0) g_s1t[131 * 128 + t] = 0.f;   // zero pad row (k=131)
    for (int i = b * 128 + t; i < N_NODES * 3; i += 16384) g_delta[i] = 0.f;
    if (b == 0 && t == 0) {
        int ok = 1;
        for (int e = 0; e < 64; e++) {
            long long v = ei[e];
            if (v < 0 || v >= (long long)N_NODES) { ok = 0; break; }
        }
        g_idx_is64 = ok;
    }
}

// ----------------- P1: per-node tables -----------------
__device__ __forceinline__ void load_w(float* s_w, const float* g, int n_f4, int tid) {
    __syncthreads();
    for (int idx = tid; idx < n_f4; idx += 256)
        ((float4*)s_w)[idx] = ((const float4*)g)[idx];
    __syncthreads();
}

// FFMA2 dense: 256 threads, 64 rows. thread: jq=tid&31 -> out cols 4jq..4jq+3
// (2 u64 accs), g=tid>>5 -> rows g*8..g*8+7. One bc2 broadcast feeds 2 FMA2.
__device__ __forceinline__ void dense128_x2(const float* __restrict__ s_in,
                                            const float* __restrict__ s_w,
                                            const float* __restrict__ bias,
                                            float* out, int ostride,
                                            int jq, int g, int nn, int do_relu)
{
    int i0 = g * 8;
    int cnt = nn - i0; if (cnt > 8) cnt = 8; if (cnt < 0) cnt = 0;
    unsigned long long acc[8][2];
    unsigned long long b0 = 0ull, b1 = 0ull;
    if (bias) {
        float4 bv = *(const float4*)(bias + 4 * jq);
        b0 = pk2(bv.x, bv.y); b1 = pk2(bv.z, bv.w);
    }
    #pragma unroll
    for (int i = 0; i < 8; i++) { acc[i][0] = b0; acc[i][1] = b1; }

    for (int k0 = 0; k0 < 128; k0 += 4) {
        unsigned long long w[4][2];
        #pragma unroll
        for (int kk = 0; kk < 4; kk++) {
            const unsigned long long* wr =
                (const unsigned long long*)(s_w + (k0 + kk) * 128 + 4 * jq);
            w[kk][0] = wr[0]; w[kk][1] = wr[1];
        }
        #pragma unroll
        for (int i = 0; i < 8; i++) {
            if (i < cnt) {
                float4 xv = *(const float4*)(s_in + (i0 + i) * 128 + k0);
                unsigned long long xb;
                xb = bc2(xv.x); FMA2(acc[i][0], xb, w[0][0]); FMA2(acc[i][1], xb, w[0][1]);
                xb = bc2(xv.y); FMA2(acc[i][0], xb, w[1][0]); FMA2(acc[i][1], xb, w[1][1]);
                xb = bc2(xv.z); FMA2(acc[i][0], xb, w[2][0]); FMA2(acc[i][1], xb, w[2][1]);
                xb = bc2(xv.w); FMA2(acc[i][0], xb, w[3][0]); FMA2(acc[i][1], xb, w[3][1]);
            }
        }
    }
    #pragma unroll
    for (int i = 0; i < 8; i++) {
        if (i < cnt) {
            float2 v0 = up2(acc[i][0]), v1 = up2(acc[i][1]);
            if (do_relu) {
                v0.x = fmaxf(v0.x, 0.f); v0.y = fmaxf(v0.y, 0.f);
                v1.x = fmaxf(v1.x, 0.f); v1.y = fmaxf(v1.y, 0.f);
            }
            float4 o; o.x = v0.x; o.y = v0.y; o.z = v1.x; o.w = v1.y;
            *(float4*)(out + (size_t)(i0 + i) * ostride + 4 * jq) = o;
        }
    }
}

__device__ __forceinline__ void gate_stage(const float* __restrict__ s_f, const float* __restrict__ s_w,
                                           float* gtab, int n0, int nn, int tid,
                                           const float* __restrict__ gw1, const float* __restrict__ gb1,
                                           const float* __restrict__ extra, int with_extra)
{
    int q = tid & 31, s8 = tid >> 5;
    for (int i = s8; i < nn; i += 8) {
        float g = with_extra ? gb1[q] : 0.f;
        for (int k0 = 0; k0 < 128; k0 += 4) {
            float4 xv = *(const float4*)(s_f + i * 128 + k0);
            g = fmaf(xv.x, s_w[k0 * 32 + q], g);
            g = fmaf(xv.y, s_w[(k0 + 1) * 32 + q], g);
            g = fmaf(xv.z, s_w[(k0 + 2) * 32 + q], g);
            g = fmaf(xv.w, s_w[(k0 + 3) * 32 + q], g);
        }
        int n = n0 + i;
        if (with_extra)
            g += gw1[q * 386 + 384] * extra[n * 2] + gw1[q * 386 + 385] * extra[n * 2 + 1];
        gtab[(size_t)n * 160 + 128 + q] = g;
    }
}

__global__ __launch_bounds__(256, 1) void node_kernel(
    const float* __restrict__ h_node, const float* __restrict__ extra,
    const float* __restrict__ gw1,
    const float* __restrict__ lb1, const float* __restrict__ lb2,
    const float* __restrict__ rb1, const float* __restrict__ rb2,
    const float* __restrict__ ib1, const float* __restrict__ gb1)
{
    extern __shared__ float sm[];
    float* s_x = sm;                // 64*128
    float* s_h = sm + 8192;
    float* s_f = sm + 16384;
    float* s_w = sm + 24576;        // 128*128
    int tid = threadIdx.x, jq = tid & 31, g = tid >> 5;
    int n0 = blockIdx.x * 64;
    int nn = N_NODES - n0; if (nn > 64) nn = 64;

    for (int idx = tid; idx < nn * 32; idx += 256)
        ((float4*)s_x)[idx] = ((const float4*)(h_node + (size_t)n0 * 128))[idx];

    load_w(s_w, g_l1t, 4096, tid);
    dense128_x2(s_x, s_w, lb1, s_h, 128, jq, g, nn, 1);
    load_w(s_w, g_l2t, 4096, tid);
    dense128_x2(s_h, s_w, lb2, s_f, 128, jq, g, nn, 0);
    load_w(s_w, g_WMLt, 4096, tid);
    dense128_x2(s_f, s_w, ib1, g_SRC + (size_t)n0 * 160, 160, jq, g, nn, 0);
    load_w(s_w, g_GLt, 1024, tid);
    gate_stage(s_f, s_w, g_SRC, n0, nn, tid, gw1, gb1, extra, 1);

    load_w(s_w, g_r1t, 4096, tid);
    dense128_x2(s_x, s_w, rb1, s_h, 128, jq, g, nn, 1);
    load_w(s_w, g_r2t, 4096, tid);
    dense128_x2(s_h, s_w, rb2, s_f, 128, jq, g, nn, 0);
    load_w(s_w, g_WMRt, 4096, tid);
    dense128_x2(s_f, s_w, (const float*)0, g_DST + (size_t)n0 * 160, 160, jq, g, nn, 0);
    load_w(s_w, g_GRt, 1024, tid);
    gate_stage(s_f, s_w, g_DST, n0, nn, tid, gw1, gb1, extra, 0);
}

// ----------------- P2: per-edge GEMM (f32x2) + epilogue + scatter ----------
__global__ __launch_bounds__(256, 1) void edge_kernel(
    const float* __restrict__ h_edge, const long long* __restrict__ ei64,
    const int* __restrict__ ei32, const float* __restrict__ rel,
    const float* __restrict__ dist,
    const float* __restrict__ iw2, const float* __restrict__ ib2,
    const float* __restrict__ gw2, const float* __restrict__ gb2)
{
    extern __shared__ float sm[];
    float* s_w   = sm;            // 20480 floats (weights), later y stride 129
    float* s_x   = sm + 20480;    // 16384
    float* s_iw2 = sm + 36864;    // 128
    float* s_gw2 = sm + 36992;    // 32
    float* s_int = sm + 37024;    // 128
    int*   s_el  = (int*)(sm + 37152);
    int*   s_er  = s_el + 128;
    int tid = threadIdx.x;
    size_t eb = (size_t)blockIdx.x * 128;

    for (int idx = tid; idx < 5120; idx += 256)
        ((float4*)s_w)[idx] = ((const float4*)g_WEt)[idx];
    {
        const float4* src = (const float4*)(h_edge + eb * 128);
        for (int idx = tid; idx < 4096; idx += 256) ((float4*)s_x)[idx] = src[idx];
    }
    if (tid < 128) {
        s_iw2[tid] = iw2[tid];
        if (tid < 32) s_gw2[tid] = gw2[tid];
        if (g_idx_is64) {
            s_el[tid] = (int)ei64[eb + tid];
            s_er[tid] = (int)ei64[N_EDGES + eb + tid];
        } else {
            s_el[tid] = ei32[eb + tid];
            s_er[tid] = ei32[N_EDGES + eb + tid];
        }
    }
    __syncthreads();

    int og = tid & 15, eg = tid >> 4;
    int o0 = og * 10, e0 = eg * 8;
    unsigned long long acc[8][5];
    #pragma unroll
    for (int i = 0; i < 8; i++)
        #pragma unroll
        for (int p = 0; p < 5; p++) acc[i][p] = 0ull;

    for (int k0 = 0; k0 < 128; k0 += 4) {
        float4 xv[8];
        #pragma unroll
        for (int i = 0; i < 8; i++)
            xv[i] = *(const float4*)(s_x + (e0 + i) * 128 + k0);
        #pragma unroll
        for (int kk = 0; kk < 4; kk++) {
            const unsigned long long* wr =
                (const unsigned long long*)(s_w + (k0 + kk) * 160 + o0);
            unsigned long long w0 = wr[0], w1 = wr[1], w2 = wr[2], w3 = wr[3], w4 = wr[4];
            #pragma unroll
            for (int i = 0; i < 8; i++) {
                unsigned long long xb = bc2(((const float*)&xv[i])[kk]);
                FMA2(acc[i][0], xb, w0); FMA2(acc[i][1], xb, w1);
                FMA2(acc[i][2], xb, w2); FMA2(acc[i][3], xb, w3);
                FMA2(acc[i][4], xb, w4);
            }
        }
    }
    __syncthreads();        // all reads of s_w / s_x done
    float* y = sm;          // y[o*129 + e], padded stride kills STS conflicts
    #pragma unroll
    for (int p = 0; p < 5; p++)
        #pragma unroll
        for (int i = 0; i < 8; i++) {
            float2 v = up2(acc[i][p]);
            y[(o0 + 2 * p) * 129 + e0 + i]     = v.x;
            y[(o0 + 2 * p + 1) * 129 + e0 + i] = v.y;
        }
    __syncthreads();

    float gate_v = 0.f;
    if (tid < 128) {                // inter dot for edge e = tid
        int e = tid, el = s_el[e], er = s_er[e];
        const float4* S = (const float4*)(g_SRC + (size_t)el * 160);
        const float4* D = (const float4*)(g_DST + (size_t)er * 160);
        float s = 0.f;
        #pragma unroll 4
        for (int j4 = 0; j4 < 32; j4++) {
            float4 u = S[j4], v = D[j4];
            int j = j4 * 4;
            s = fmaf(fmaxf(y[j * 129 + e] + u.x + v.x, 0.f), s_iw2[j], s);
            s = fmaf(fmaxf(y[(j + 1) * 129 + e] + u.y + v.y, 0.f), s_iw2[j + 1], s);
            s = fmaf(fmaxf(y[(j + 2) * 129 + e] + u.z + v.z, 0.f), s_iw2[j + 2], s);
            s = fmaf(fmaxf(y[(j + 3) * 129 + e] + u.w + v.w, 0.f), s_iw2[j + 3], s);
        }
        s_int[e] = s + ib2[0];
    } else {                        // gate dot for edge e = tid-128
        int e = tid - 128, el = s_el[e], er = s_er[e];
        const float4* S = (const float4*)(g_SRC + (size_t)el * 160 + 128);
        const float4* D = (const float4*)(g_DST + (size_t)er * 160 + 128);
        float g = 0.f;
        #pragma unroll
        for (int q4 = 0; q4 < 8; q4++) {
            float4 u = S[q4], v = D[q4];
            int j = 128 + q4 * 4, q = q4 * 4;
            g = fmaf(fmaxf(y[j * 129 + e] + u.x + v.x, 0.f), s_gw2[q], g);
            g = fmaf(fmaxf(y[(j + 1) * 129 + e] + u.y + v.y, 0.f), s_gw2[q + 1], g);
            g = fmaf(fmaxf(y[(j + 2) * 129 + e] + u.z + v.z, 0.f), s_gw2[q + 2], g);
            g = fmaf(fmaxf(y[(j + 3) * 129 + e] + u.w + v.w, 0.f), s_gw2[q + 3], g);
        }
        gate_v = g + gb2[0];
    }
    __syncthreads();
    if (tid >= 128) {
        int e = tid - 128, el = s_el[e];
        float w = s_int[e] * (1.f / (1.f + expf(-gate_v)));
        float d = dist[eb + e];
        float coef = w * 5.f / ((d + 1e-6f) * (d + 5.f));
        size_t rb = (eb + e) * 3;
        atomicAdd(&g_delta[el * 3 + 0], coef * rel[rb + 0]);
        atomicAdd(&g_delta[el * 3 + 1], coef * rel[rb + 1]);
        atomicAdd(&g_delta[el * 3 + 2], coef * rel[rb + 2]);
    }
}

// ----------------- P3: norm + scale MLP + output (batched, 2 barriers) -----
__global__ __launch_bounds__(256, 1) void final_kernel(
    const float* __restrict__ h_node, const float* __restrict__ extra,
    const float* __restrict__ sb1, const float* __restrict__ sw2,
    const float* __restrict__ sb2, float* __restrict__ out)
{
    extern __shared__ float sm[];
    float* s_w   = sm;            // 132*128 = 16896
    float* s_x   = sm + 16896;    // 64*132  = 8448
    float* s_red = sm + 25344;    // 64*33   = 2112
    float* s_w2  = sm + 27456;    // 128
    int tid = threadIdx.x, jq = tid & 31, g = tid >> 5;
    int n0 = blockIdx.x * 64;
    int nn = N_NODES - n0; if (nn > 64) nn = 64;

    for (int idx = tid; idx < 4224; idx += 256)
        ((float4*)s_w)[idx] = ((const float4*)g_s1t)[idx];
    for (int idx = tid; idx < nn * 32; idx += 256) {
        int i = idx >> 5, c = idx & 31;
        *(float4*)(s_x + i * 132 + 4 * c) =
            ((const float4*)(h_node + (size_t)(n0 + i) * 128))[c];
    }
    if (tid < 64 && tid < nn) {
        int n = n0 + tid;
        s_x[tid * 132 + 128] = extra[n * 2];
        s_x[tid * 132 + 129] = extra[n * 2 + 1];
        float dx = g_delta[n * 3], dy = g_delta[n * 3 + 1], dz = g_delta[n * 3 + 2];
        s_x[tid * 132 + 130] = sqrtf(dx * dx + dy * dy + dz * dz);
        s_x[tid * 132 + 131] = 0.f;
    }
    if (tid < 128) s_w2[tid] = sw2[tid];
    __syncthreads();

    int i0 = g * 8;
    int cnt = nn - i0; if (cnt > 8) cnt = 8; if (cnt < 0) cnt = 0;
    unsigned long long acc[8][2];
    {
        float4 bv = *(const float4*)(sb1 + 4 * jq);
        unsigned long long b0 = pk2(bv.x, bv.y), b1 = pk2(bv.z, bv.w);
        #pragma unroll
        for (int i = 0; i < 8; i++) { acc[i][0] = b0; acc[i][1] = b1; }
    }
    for (int k0 = 0; k0 < 132; k0 += 4) {
        unsigned long long w[4][2];
        #pragma unroll
        for (int kk = 0; kk < 4; kk++) {
            const unsigned long long* wr =
                (const unsigned long long*)(s_w + (k0 + kk) * 128 + 4 * jq);
            w[kk][0] = wr[0]; w[kk][1] = wr[1];
        }
        #pragma unroll
        for (int i = 0; i < 8; i++) {
            if (i < cnt) {
                float4 xv = *(const float4*)(s_x + (i0 + i) * 132 + k0);
                unsigned long long xb;
                xb = bc2(xv.x); FMA2(acc[i][0], xb, w[0][0]); FMA2(acc[i][1], xb, w[0][1]);
                xb = bc2(xv.y); FMA2(acc[i][0], xb, w[1][0]); FMA2(acc[i][1], xb, w[1][1]);
                xb = bc2(xv.z); FMA2(acc[i][0], xb, w[2][0]); FMA2(acc[i][1], xb, w[2][1]);
                xb = bc2(xv.w); FMA2(acc[i][0], xb, w[3][0]); FMA2(acc[i][1], xb, w[3][1]);
            }
        }
    }
    {
        float4 w2v = *(const float4*)(s_w2 + 4 * jq);
        #pragma unroll
        for (int i = 0; i < 8; i++) {
            if (i < cnt) {
                float2 a0 = up2(acc[i][0]), a1 = up2(acc[i][1]);
                float p = fmaxf(a0.x, 0.f) * w2v.x + fmaxf(a0.y, 0.f) * w2v.y
                        + fmaxf(a1.x, 0.f) * w2v.z + fmaxf(a1.y, 0.f) * w2v.w;
                s_red[(i0 + i) * 33 + jq] = p;
            }
        }
    }
    __syncthreads();
    if (tid < 64 && tid < nn) {
        int n = n0 + tid;
        float s = 0.f;
        #pragma unroll
        for (int q = 0; q < 32; q++) s += s_red[tid * 33 + q];
        float sc = 1.f / (1.f + expf(-(s + sb2[0])));
        out[n * 3 + 0] = g_delta[n * 3 + 0] * sc;
        out[n * 3 + 1] = g_delta[n * 3 + 1] * sc;
        out[n * 3 + 2] = g_delta[n * 3 + 2] * sc;
    }
}

// ----------------- launch -----------------
extern "C" void kernel_launch(void* const* d_in, const int* in_sizes, int n_in,
                              void* d_out, int out_size)
{
    const float* h_node = (const float*)d_in[0];
    const float* h_edge = (const float*)d_in[1];
    const void*  ei     = d_in[2];
    const float* rel    = (const float*)d_in[3];
    const float* dist   = (const float*)d_in[4];
    const float* extra  = (const float*)d_in[5];
    const float* lw1 = (const float*)d_in[6];  const float* lb1 = (const float*)d_in[7];
    const float* lw2 = (const float*)d_in[8];  const float* lb2 = (const float*)d_in[9];
    const float* rw1 = (const float*)d_in[10]; const float* rb1 = (const float*)d_in[11];
    const float* rw2 = (const float*)d_in[12]; const float* rb2 = (const float*)d_in[13];
    const float* bond  = (const float*)d_in[14];
    const float* nodeb = (const float*)d_in[15];
    const float* iw1 = (const float*)d_in[16]; const float* ib1 = (const float*)d_in[17];
    const float* iw2 = (const float*)d_in[18]; const float* ib2 = (const float*)d_in[19];
    const float* gw1 = (const float*)d_in[20]; const float* gb1 = (const float*)d_in[21];
    const float* gw2 = (const float*)d_in[22]; const float* gb2 = (const float*)d_in[23];
    const float* sw1 = (const float*)d_in[24]; const float* sb1 = (const float*)d_in[25];
    const float* sw2 = (const float*)d_in[26]; const float* sb2 = (const float*)d_in[27];

    const int NODE_SMEM = 163840;   // 40960 floats
    const int EDGE_SMEM = 149632;
    const int FIN_SMEM  = 110336;   // 27584 floats

    cudaFuncSetAttribute(node_kernel, cudaFuncAttributeMaxDynamicSharedMemorySize, NODE_SMEM);
    cudaFuncSetAttribute(edge_kernel, cudaFuncAttributeMaxDynamicSharedMemorySize, EDGE_SMEM);
    cudaFuncSetAttribute(final_kernel, cudaFuncAttributeMaxDynamicSharedMemorySize, FIN_SMEM);

    prep_kernel<<<128, 128>>>(iw1, bond, nodeb, gw1, lw1, lw2, rw1, rw2, sw1,
                              (const long long*)ei);
    node_kernel<<<(N_NODES + 63) / 64, 256, NODE_SMEM>>>(h_node, extra, gw1,
                                                         lb1, lb2, rb1, rb2, ib1, gb1);
    edge_kernel<<<N_EDGES / 128, 256, EDGE_SMEM>>>(h_edge, (const long long*)ei,
                                                   (const int*)ei, rel, dist,
                                                   iw2, ib2, gw2, gb2);
    final_kernel<<<(N_NODES + 63) / 64, 256, FIN_SMEM>>>(h_node, extra, sb1, sw2, sb2,
                                                         (float*)d_out);
}